// round 13
// baseline (speedup 1.0000x reference)
#include <cuda_runtime.h>

// Problem dims (fixed by the dataset)
#define Bdim 16
#define Sdim 4096
#define Hdim 512
#define Gdim 2
#define Vdim 320
#define Ddim 128
#define GDdim 256
#define NTOK (Bdim * Sdim)           // 65536
#define TOK 32
#define NCTA (NTOK / TOK)            // 2048

// Output layout (concatenated reference returns)
#define Q_OFF    0
#define ENC_OFF  16777216
#define DIST_OFF 58720256
#define PERP_OFF 100663296

#define TAU 0.0625f

// device scratch
__device__ float  g_Wp[Hdim * GDdim];        // W full fp32, fragment-paired
__device__ float  g_Cp[Gdim * Vdim * Ddim];  // codevectors rna-tf32, fragment-paired
__device__ double g_c2d[Gdim * Vdim];        // exact ||c||^2
__device__ int    g_counts[Gdim * Vdim];
__device__ int    g_done = 0;

__device__ __forceinline__ void split2(float x, unsigned& hi, unsigned& lo) {
    unsigned xb = __float_as_uint(x);
    hi = xb & 0xFFFFE000u;
    lo = __float_as_uint(x - __uint_as_float(hi));
}

__device__ __forceinline__ void mma_tf32(float* c, const unsigned* a, const unsigned* b) {
    asm volatile(
        "mma.sync.aligned.m16n8k8.row.col.f32.tf32.tf32.f32 "
        "{%0,%1,%2,%3}, {%4,%5,%6,%7}, {%8,%9}, {%0,%1,%2,%3};\n"
        : "+f"(c[0]), "+f"(c[1]), "+f"(c[2]), "+f"(c[3])
        : "r"(a[0]), "r"(a[1]), "r"(a[2]), "r"(a[3]), "r"(b[0]), "r"(b[1]));
}

__device__ __forceinline__ void cpa16(float* s, const float* g) {
    unsigned sa = (unsigned)__cvta_generic_to_shared(s);
    asm volatile("cp.async.cg.shared.global [%0], [%1], 16;\n" :: "r"(sa), "l"(g));
}
#define CPA_COMMIT() asm volatile("cp.async.commit_group;\n" ::: "memory")
#define CPA_WAIT0()  asm volatile("cp.async.wait_group 0;\n" ::: "memory")

// ---------------------------------------------------------------------------
// Prep: counts=0, exact c2, W fragment-paired (full fp32), C paired tf32.
// ---------------------------------------------------------------------------
__global__ void prep_kernel(const float* __restrict__ W, const float* __restrict__ C) {
    int tid = blockIdx.x * blockDim.x + threadIdx.x;  // 131072 threads
    if (tid == 0) g_done = 0;
    if (tid < Hdim * GDdim) {
        int e = tid;
        int k = e >> 8, n = e & 255;
        int kc = k >> 4, k16 = k & 15, kk = k16 >> 3, k8 = k16 & 7;
        int s = n >> 3, l = (k8 & 3) + ((n & 7) << 2), slot = k8 >> 2;
        g_Wp[(kc << 12) + (((kk << 5) + s) << 6) + 2 * l + slot] = W[e];
    }
    if (tid < Gdim * Vdim * Ddim) {
        int e = tid;
        int g = e / (Vdim * Ddim);
        int rem = e - g * (Vdim * Ddim);
        int v = rem >> 7, d = rem & 127;
        int kc = d >> 3, k8 = d & 7;
        int s = v >> 3, l = (k8 & 3) + ((v & 7) << 2), slot = k8 >> 2;
        unsigned r;
        asm("cvt.rna.tf32.f32 %0, %1;" : "=r"(r) : "f"(C[e]));
        g_Cp[(((g << 4) + kc) * 40 + s) * 64 + 2 * l + slot] = __uint_as_float(r);
    }
    int gw = tid >> 5, lane = tid & 31;
    if (gw < Gdim * Vdim) {
        float4 cv = *(const float4*)(C + (size_t)gw * Ddim + (lane << 2));
        double s = 0.0;
        s = fma((double)cv.x, (double)cv.x, s);
        s = fma((double)cv.y, (double)cv.y, s);
        s = fma((double)cv.z, (double)cv.z, s);
        s = fma((double)cv.w, (double)cv.w, s);
#pragma unroll
        for (int off = 16; off >= 1; off >>= 1)
            s += __shfl_xor_sync(0xffffffffu, s, off);
        if (lane == 0) { g_c2d[gw] = s; g_counts[gw] = 0; }
    }
}

// ---------------------------------------------------------------------------
// smem layout (float slots)
// ---------------------------------------------------------------------------
#define SM_HSP   0       // 8192
#define SM_BUF   8192    // 16384: stage1 W double (2x8192) / stage2 C double (2x5120)
#define SM_XP    24576   // 2048: double-buffered X paired (2x1024, 32 k each)
#define SM_BIAS  26624   // 256
#define SM_C2F   26880   // 640 (reused as entropy scratch in fused perp)
#define SM_H2P   27520   // 128
#define SM_FMI   27648   // 32 (ints)
#define SM_RCNT  27680   // 32 (ints)
#define SM_RVID  27712   // 512 (ints): 32 rows x 16 slots
#define SM_LAST  28224   // 1 (int)
#define SM_FLOATS 28228  // 112,912 B -> 2 CTAs/SM

extern __shared__ float smem[];

__global__ __launch_bounds__(256, 2)
void main_kernel(const float* __restrict__ X,   // [B*S, 512]
                 const float* __restrict__ bias,// [256]
                 const float* __restrict__ C,   // [2,320,128]
                 float* __restrict__ out)
{
    float*  hsp  = smem + SM_HSP;
    float*  buf  = smem + SM_BUF;
    float*  Xp   = smem + SM_XP;
    float*  bs   = smem + SM_BIAS;
    float*  c2f  = smem + SM_C2F;
    float*  h2p  = smem + SM_H2P;
    int*    fmi  = (int*)(smem + SM_FMI);
    int*    rcnt = (int*)(smem + SM_RCNT);
    int*    rvid = (int*)(smem + SM_RVID);
    int*    slast= (int*)(smem + SM_LAST);

    const int tx   = threadIdx.x;
    const int lane = tx & 31;
    const int w    = tx >> 5;
    const int wm   = w & 1;
    const int wn   = w >> 1;
    const int t0   = blockIdx.x * TOK;
    const int r0   = (wm << 4) + (lane >> 2);
    const int r1   = r0 + 8;
    const int lq2  = (lane & 3) << 1;

    const int ltok = tx >> 3;      // 0..31 (token)
    const int lqx  = tx & 7;       // 0..7  (4 k's each -> 32 k per iteration)
    const int xkk  = lqx >> 1;     // kk block 0..3
    const int xslt = lqx & 1;      // pair slot
    const int xpo  = (xkk << 8) + (ltok << 3) + xslt;
    const float* xrow = X + (size_t)(t0 + ltok) * Hdim + (lqx << 2);

    // preload c2f and bias (covered by first __syncthreads)
    c2f[tx]       = (float)g_c2d[tx];
    c2f[tx + 256] = (float)g_c2d[tx + 256];
    if (tx < 128) c2f[tx + 512] = (float)g_c2d[tx + 512];
    bs[tx] = bias[tx];

    // ============ Stage 1: h = X @ W + b  (tf32x3, 32-k iterations) =========
    float acc[8][4];
#pragma unroll
    for (int i = 0; i < 8; i++)
#pragma unroll
        for (int j = 0; j < 4; j++) acc[i][j] = 0.f;

    // preload iteration 0 (X 32-k slice + W chunk-pair 0 = 32KB)
    {
        float4 xv = *(const float4*)(xrow);
        Xp[xpo] = xv.x; Xp[xpo + 2] = xv.y; Xp[xpo + 4] = xv.z; Xp[xpo + 6] = xv.w;
#pragma unroll
        for (int q = 0; q < 8; q++)
            cpa16(buf + ((tx + (q << 8)) << 2), g_Wp + ((tx + (q << 8)) << 2));
        CPA_COMMIT();
    }
    CPA_WAIT0();
    __syncthreads();

    for (int kc = 0; kc < 16; kc++) {
        const int cur = kc & 1, nxt = cur ^ 1;
        if (kc < 15) {
            float4 xv = *(const float4*)(xrow + ((kc + 1) << 5));
            float* xp = Xp + nxt * 1024 + xpo;
            xp[0] = xv.x; xp[2] = xv.y; xp[4] = xv.z; xp[6] = xv.w;
            const float* sW = g_Wp + ((kc + 1) << 13);
            float* dW = buf + nxt * 8192;
#pragma unroll
            for (int q = 0; q < 8; q++)
                cpa16(dW + ((tx + (q << 8)) << 2), sW + ((tx + (q << 8)) << 2));
            CPA_COMMIT();
        }
        const float* bw = buf + cur * 8192;
        const float* xp = Xp + cur * 1024;
#pragma unroll
        for (int kk = 0; kk < 4; kk++) {
            float2 pa = *(float2*)&xp[(kk << 8) + (r0 << 3) + lq2];
            float2 pb = *(float2*)&xp[(kk << 8) + (r1 << 3) + lq2];
            unsigned ah[4], al[4];
            split2(pa.x, ah[0], al[0]); split2(pb.x, ah[1], al[1]);
            split2(pa.y, ah[2], al[2]); split2(pb.y, ah[3], al[3]);
#pragma unroll
            for (int s8 = 0; s8 < 8; s8++) {
                float2 pw = *(float2*)&bw[(((kk << 5) + (wn << 3) + s8) << 6) + (lane << 1)];
                unsigned bh[2], bl[2];
                split2(pw.x, bh[0], bl[0]);
                split2(pw.y, bh[1], bl[1]);
                mma_tf32(acc[s8], ah, bh);
                mma_tf32(acc[s8], ah, bl);
                mma_tf32(acc[s8], al, bh);
            }
        }
        CPA_WAIT0();
        __syncthreads();
    }

    // prefetch stage-2 group-0 chunk-0 into buf[0:5120)
    {
#pragma unroll
        for (int q = 0; q < 5; q++)
            cpa16(buf + ((tx + (q << 8)) << 2), g_Cp + ((tx + (q << 8)) << 2));
        CPA_COMMIT();
    }

    // stage-1 epilogue: +bias, h2 partials, store h fragment-paired
    {
        float h2a = 0.f, h2b = 0.f;
#pragma unroll
        for (int s8 = 0; s8 < 8; s8++) {
            int s   = (wn << 3) + s8;
            int col = (s << 3) + lq2;
            float2 bb = *(float2*)&bs[col];
            float v0 = acc[s8][0] + bb.x;
            float v1 = acc[s8][1] + bb.y;
            float v2 = acc[s8][2] + bb.x;
            float v3 = acc[s8][3] + bb.y;
            h2a = fmaf(v0, v0, h2a); h2a = fmaf(v1, v1, h2a);
            h2b = fmaf(v2, v2, h2b); h2b = fmaf(v3, v3, h2b);
            int g = col >> 7, cg = col & 127;
            int kc = cg >> 3, k8 = cg & 7;
            int p0 = k8 & 3, sl0 = k8 >> 2;
            int k8b = k8 + 1, p1 = k8b & 3, sl1 = k8b >> 2;
            int base = (((g << 4) + kc) << 5);
            hsp[((base + r0) << 3) + (p0 << 1) + sl0] = v0;
            hsp[((base + r0) << 3) + (p1 << 1) + sl1] = v1;
            hsp[((base + r1) << 3) + (p0 << 1) + sl0] = v2;
            hsp[((base + r1) << 3) + (p1 << 1) + sl1] = v3;
        }
        h2a += __shfl_xor_sync(0xffffffffu, h2a, 1);
        h2a += __shfl_xor_sync(0xffffffffu, h2a, 2);
        h2b += __shfl_xor_sync(0xffffffffu, h2b, 1);
        h2b += __shfl_xor_sync(0xffffffffu, h2b, 2);
        if ((lane & 3) == 0) {
            h2p[(wn << 5) + r0] = h2a;
            h2p[(wn << 5) + r1] = h2b;
        }
        if (tx < 32) rcnt[tx] = 0;   // ready for group 0 flagging
    }
    CPA_WAIT0();
    __syncthreads();

    // ============ Stage 2: hc (tf32x1, pipelined) + exact-rescue argmin =====
    const int bidx  = t0 >> 12;
    const int sbase = t0 & 4095;

    for (int g = 0; g < Gdim; g++) {
        float acc2[10][4];
#pragma unroll
        for (int i = 0; i < 10; i++)
#pragma unroll
            for (int j = 0; j < 4; j++) acc2[i][j] = 0.f;

        for (int kc2 = 0; kc2 < 8; kc2++) {
            const int cur = kc2 & 1, nxt = cur ^ 1;
            if (kc2 < 7) {
                const float* src = g_Cp + ((g << 4) + ((kc2 + 1) << 1)) * 2560;
                float* dst = buf + nxt * 5120;
#pragma unroll
                for (int q = 0; q < 5; q++)
                    cpa16(dst + ((tx + (q << 8)) << 2), src + ((tx + (q << 8)) << 2));
                CPA_COMMIT();
            } else if (g == 0) {
                const float* src = g_Cp + 16 * 2560;   // g=1, chunk 0
                float* dst = buf + nxt * 5120;
#pragma unroll
                for (int q = 0; q < 5; q++)
                    cpa16(dst + ((tx + (q << 8)) << 2), src + ((tx + (q << 8)) << 2));
                CPA_COMMIT();
            }
            const float* bc = buf + cur * 5120;
#pragma unroll
            for (int kk = 0; kk < 2; kk++) {
                int kcx = (kc2 << 1) + kk;
                int hb = (((g << 4) + kcx) << 5);
                float2 pa = *(float2*)&hsp[((hb + r0) << 3) + lq2];
                float2 pb = *(float2*)&hsp[((hb + r1) << 3) + lq2];
                unsigned a[4] = {__float_as_uint(pa.x), __float_as_uint(pb.x),
                                 __float_as_uint(pa.y), __float_as_uint(pb.y)};
#pragma unroll
                for (int j = 0; j < 10; j++) {
                    float2 pw = *(float2*)&bc[((kk * 40 + wn * 10 + j) << 6) + (lane << 1)];
                    unsigned b[2] = {__float_as_uint(pw.x), __float_as_uint(pw.y)};
                    mma_tf32(acc2[j], a, b);
                }
            }
            CPA_WAIT0();
            __syncthreads();
        }

        // ---- epilogue: keys (cached into acc2), distances out, local min ---
        const float h2f0 = h2p[((2 * g) << 5) + r0] + h2p[((2 * g + 1) << 5) + r0];
        const float h2f1 = h2p[((2 * g) << 5) + r1] + h2p[((2 * g + 1) << 5) + r1];
        const size_t row0 = ((size_t)((g * Bdim + bidx) * Sdim) + sbase + r0) * (size_t)Vdim;
        const size_t row1 = ((size_t)((g * Bdim + bidx) * Sdim) + sbase + r1) * (size_t)Vdim;

        float m0 = 1e30f, m1 = 1e30f;
#pragma unroll
        for (int j = 0; j < 10; j++) {
            int v0 = ((wn * 10 + j) << 3) + lq2;
            float2 cc = *(float2*)&c2f[g * Vdim + v0];
            float k00 = fmaf(-2.f, acc2[j][0], cc.x);
            float k01 = fmaf(-2.f, acc2[j][1], cc.y);
            float k10 = fmaf(-2.f, acc2[j][2], cc.x);
            float k11 = fmaf(-2.f, acc2[j][3], cc.y);
            acc2[j][0] = k00; acc2[j][1] = k01;   // cache keys (hc dead now)
            acc2[j][2] = k10; acc2[j][3] = k11;
            *(float2*)(out + DIST_OFF + row0 + v0) = make_float2(h2f0 + k00, h2f0 + k01);
            *(float2*)(out + DIST_OFF + row1 + v0) = make_float2(h2f1 + k10, h2f1 + k11);
            m0 = fminf(m0, fminf(k00, k01));
            m1 = fminf(m1, fminf(k10, k11));
        }
        // warp-local row min (over this warp's 80 values per row). A local
        // threshold >= global threshold -> flagged superset still contains the
        // true argmin; rescue decides on exact keys, so result is unchanged.
#pragma unroll
        for (int off = 1; off <= 2; off <<= 1) {
            m0 = fminf(m0, __shfl_xor_sync(0xffffffffu, m0, off));
            m1 = fminf(m1, __shfl_xor_sync(0xffffffffu, m1, off));
        }
        // flag candidates within TAU of the warp-local min (rcnt pre-zeroed)
        {
            float thr0 = m0 + TAU, thr1 = m1 + TAU;
#pragma unroll
            for (int j = 0; j < 10; j++) {
                int v0 = ((wn * 10 + j) << 3) + lq2;
                if (acc2[j][0] <= thr0) { int s = atomicAdd(&rcnt[r0], 1); if (s < 16) rvid[(r0 << 4) + s] = v0; }
                if (acc2[j][1] <= thr0) { int s = atomicAdd(&rcnt[r0], 1); if (s < 16) rvid[(r0 << 4) + s] = v0 + 1; }
                if (acc2[j][2] <= thr1) { int s = atomicAdd(&rcnt[r1], 1); if (s < 16) rvid[(r1 << 4) + s] = v0; }
                if (acc2[j][3] <= thr1) { int s = atomicAdd(&rcnt[r1], 1); if (s < 16) rvid[(r1 << 4) + s] = v0 + 1; }
            }
        }
        __syncthreads();
        // exact rescue: warp w handles rows 4w..4w+3
        {
#pragma unroll
            for (int q = 0; q < 4; q++) {
                int r = (w << 2) + q;
                double hd[4];
#pragma unroll
                for (int e = 0; e < 4; e++) {
                    int d = (lane << 2) + e;
                    int kcq = d >> 3, k8 = d & 7;
                    hd[e] = (double)hsp[(((((g << 4) + kcq) << 5) + r) << 3) + ((k8 & 3) << 1) + (k8 >> 2)];
                }
                int n = rcnt[r]; if (n > 16) n = 16;
                double bk = 1e300; int bv = 0x7fffffff;
                for (int i = 0; i < n; i++) {
                    int v = rvid[(r << 4) + i];
                    float4 cv = *(const float4*)(C + ((size_t)(g * Vdim + v)) * Ddim + (lane << 2));
                    double dot = 0.0;
                    dot = fma(hd[0], (double)cv.x, dot);
                    dot = fma(hd[1], (double)cv.y, dot);
                    dot = fma(hd[2], (double)cv.z, dot);
                    dot = fma(hd[3], (double)cv.w, dot);
#pragma unroll
                    for (int off = 16; off >= 1; off >>= 1)
                        dot += __shfl_xor_sync(0xffffffffu, dot, off);
                    double key = fma(-2.0, dot, g_c2d[g * Vdim + v]);
                    if (key < bk || (key == bk && v < bv)) { bk = key; bv = v; }
                }
                if (lane == 0) {
                    fmi[r] = bv;
                    atomicAdd(&g_counts[g * Vdim + bv], 1);
                }
            }
        }
        __syncthreads();
        // encodings + quantized gather (+ rezero rcnt for next group)
        const int mi0 = fmi[r0], mi1 = fmi[r1];
#pragma unroll
        for (int j = 0; j < 10; j++) {
            int v0 = ((wn * 10 + j) << 3) + lq2;
            *(float2*)(out + ENC_OFF + row0 + v0) =
                make_float2(v0 == mi0 ? 1.f : 0.f, v0 + 1 == mi0 ? 1.f : 0.f);
            *(float2*)(out + ENC_OFF + row1 + v0) =
                make_float2(v0 == mi1 ? 1.f : 0.f, v0 + 1 == mi1 ? 1.f : 0.f);
        }
        {
            int task = tx >> 3, l8 = tx & 7;
            int mi = fmi[task];
            const float4* cs = (const float4*)(C + ((size_t)(g * Vdim + mi)) * Ddim + (l8 << 4));
            float4* qd = (float4*)(out + Q_OFF + (size_t)(t0 + task) * GDdim + g * Ddim + (l8 << 4));
            qd[0] = cs[0]; qd[1] = cs[1]; qd[2] = cs[2]; qd[3] = cs[3];
        }
        if (tx < 32) rcnt[tx] = 0;
        __syncthreads();
    }

    // ============ Fused perplexity: last CTA computes it ====================
    __threadfence();
    if (tx == 0) slast[0] = (atomicAdd(&g_done, 1) == NCTA - 1) ? 1 : 0;
    __syncthreads();
    if (slast[0]) {
        __threadfence();
        // reuse c2f region as entropy scratch
        for (int i = tx; i < Gdim * Vdim; i += 256) {
            float p = (float)g_counts[i] * (1.0f / (float)NTOK);
            p = fminf(fmaxf(p, 1e-10f), 1.0f);
            c2f[i] = p * logf(p + 1e-10f);
        }
        __syncthreads();
        if (tx == 0) {
            float s0 = 0.f, s1 = 0.f;
            for (int v = 0; v < Vdim; v++) s0 += c2f[v];
            for (int v = 0; v < Vdim; v++) s1 += c2f[Vdim + v];
            out[PERP_OFF] = 0.5f * (expf(-s0) + expf(-s1));
            g_done = 0;   // reset for next graph replay
        }
    }
}

// ---------------------------------------------------------------------------
extern "C" void kernel_launch(void* const* d_in, const int* in_sizes, int n_in,
                              void* d_out, int out_size) {
    const float* X    = (const float*)d_in[0];
    const float* W    = (const float*)d_in[1];
    const float* bias = (const float*)d_in[2];
    const float* C    = (const float*)d_in[3];
    float* out = (float*)d_out;

    cudaFuncSetAttribute(main_kernel, cudaFuncAttributeMaxDynamicSharedMemorySize,
                         SM_FLOATS * sizeof(float));

    prep_kernel<<<512, 256>>>(W, C);
    main_kernel<<<NCTA, 256, SM_FLOATS * sizeof(float)>>>(X, bias, C, out);
}

// round 14
// speedup vs baseline: 1.6056x; 1.6056x over previous
#include <cuda_runtime.h>

// Problem dims (fixed by the dataset)
#define Bdim 16
#define Sdim 4096
#define Hdim 512
#define Gdim 2
#define Vdim 320
#define Ddim 128
#define GDdim 256
#define NTOK (Bdim * Sdim)           // 65536
#define TOK 32
#define NCTA (NTOK / TOK)            // 2048

// Output layout (concatenated reference returns)
#define Q_OFF    0
#define ENC_OFF  16777216
#define DIST_OFF 58720256
#define PERP_OFF 100663296

#define TAU 0.0625f

// device scratch
__device__ float  g_Wp[Hdim * GDdim];        // W full fp32, fragment-paired
__device__ float  g_Cp[Gdim * Vdim * Ddim];  // codevectors rna-tf32, fragment-paired
__device__ double g_c2d[Gdim * Vdim];        // exact ||c||^2
__device__ int    g_counts[Gdim * Vdim];
__device__ int    g_done = 0;

__device__ __forceinline__ void split2(float x, unsigned& hi, unsigned& lo) {
    unsigned xb = __float_as_uint(x);
    hi = xb & 0xFFFFE000u;
    lo = __float_as_uint(x - __uint_as_float(hi));
}

__device__ __forceinline__ void mma_tf32(float* c, const unsigned* a, const unsigned* b) {
    asm volatile(
        "mma.sync.aligned.m16n8k8.row.col.f32.tf32.tf32.f32 "
        "{%0,%1,%2,%3}, {%4,%5,%6,%7}, {%8,%9}, {%0,%1,%2,%3};\n"
        : "+f"(c[0]), "+f"(c[1]), "+f"(c[2]), "+f"(c[3])
        : "r"(a[0]), "r"(a[1]), "r"(a[2]), "r"(a[3]), "r"(b[0]), "r"(b[1]));
}

__device__ __forceinline__ void cpa16(float* s, const float* g) {
    unsigned sa = (unsigned)__cvta_generic_to_shared(s);
    asm volatile("cp.async.cg.shared.global [%0], [%1], 16;\n" :: "r"(sa), "l"(g));
}
#define CPA_COMMIT() asm volatile("cp.async.commit_group;\n" ::: "memory")
#define CPA_WAIT0()  asm volatile("cp.async.wait_group 0;\n" ::: "memory")

// ---------------------------------------------------------------------------
// Prep: counts=0, exact c2, W fragment-paired (full fp32), C paired tf32.
// ---------------------------------------------------------------------------
__global__ void prep_kernel(const float* __restrict__ W, const float* __restrict__ C) {
    int tid = blockIdx.x * blockDim.x + threadIdx.x;  // 131072 threads
    if (tid == 0) g_done = 0;
    if (tid < Hdim * GDdim) {
        int e = tid;
        int k = e >> 8, n = e & 255;
        int kc = k >> 4, k16 = k & 15, kk = k16 >> 3, k8 = k16 & 7;
        int s = n >> 3, l = (k8 & 3) + ((n & 7) << 2), slot = k8 >> 2;
        g_Wp[(kc << 12) + (((kk << 5) + s) << 6) + 2 * l + slot] = W[e];
    }
    if (tid < Gdim * Vdim * Ddim) {
        int e = tid;
        int g = e / (Vdim * Ddim);
        int rem = e - g * (Vdim * Ddim);
        int v = rem >> 7, d = rem & 127;
        int kc = d >> 3, k8 = d & 7;
        int s = v >> 3, l = (k8 & 3) + ((v & 7) << 2), slot = k8 >> 2;
        unsigned r;
        asm("cvt.rna.tf32.f32 %0, %1;" : "=r"(r) : "f"(C[e]));
        g_Cp[(((g << 4) + kc) * 40 + s) * 64 + 2 * l + slot] = __uint_as_float(r);
    }
    int gw = tid >> 5, lane = tid & 31;
    if (gw < Gdim * Vdim) {
        float4 cv = *(const float4*)(C + (size_t)gw * Ddim + (lane << 2));
        double s = 0.0;
        s = fma((double)cv.x, (double)cv.x, s);
        s = fma((double)cv.y, (double)cv.y, s);
        s = fma((double)cv.z, (double)cv.z, s);
        s = fma((double)cv.w, (double)cv.w, s);
#pragma unroll
        for (int off = 16; off >= 1; off >>= 1)
            s += __shfl_xor_sync(0xffffffffu, s, off);
        if (lane == 0) { g_c2d[gw] = s; g_counts[gw] = 0; }
    }
}

// ---------------------------------------------------------------------------
// smem layout (float slots) — R10 layout + SM_LAST for fused perplexity
// ---------------------------------------------------------------------------
#define SM_HSP   0       // 8192
#define SM_BUF   8192    // 16384: stage1 W double (2x8192) / stage2 C double (2x5120)
#define SM_XP    24576   // 2048: double-buffered X paired (2x1024, 32 k each)
#define SM_BIAS  26624   // 256
#define SM_C2F   26880   // 640 (reused as entropy scratch in fused perp)
#define SM_H2P   27520   // 128
#define SM_AMV   27648   // 128
#define SM_FMV   27776   // 32
#define SM_FMI   27808   // 32 (ints)
#define SM_RCNT  27840   // 32 (ints)
#define SM_RVID  27872   // 384 (ints): 32 rows x 12 slots
#define SM_LAST  28256   // 1 (int)
#define SM_FLOATS 28260  // 113,040 B -> 2 CTAs/SM

extern __shared__ float smem[];

__global__ __launch_bounds__(256, 2)
void main_kernel(const float* __restrict__ X,   // [B*S, 512]
                 const float* __restrict__ bias,// [256]
                 const float* __restrict__ C,   // [2,320,128]
                 float* __restrict__ out)
{
    float*  hsp  = smem + SM_HSP;
    float*  buf  = smem + SM_BUF;
    float*  Xp   = smem + SM_XP;
    float*  bs   = smem + SM_BIAS;
    float*  c2f  = smem + SM_C2F;
    float*  h2p  = smem + SM_H2P;
    float*  amv  = smem + SM_AMV;
    float*  fmv  = smem + SM_FMV;
    int*    fmi  = (int*)(smem + SM_FMI);
    int*    rcnt = (int*)(smem + SM_RCNT);
    int*    rvid = (int*)(smem + SM_RVID);
    int*    slast= (int*)(smem + SM_LAST);

    const int tx   = threadIdx.x;
    const int lane = tx & 31;
    const int w    = tx >> 5;
    const int wm   = w & 1;
    const int wn   = w >> 1;
    const int t0   = blockIdx.x * TOK;
    const int r0   = (wm << 4) + (lane >> 2);
    const int r1   = r0 + 8;
    const int lq2  = (lane & 3) << 1;

    const int ltok = tx >> 3;      // 0..31 (token)
    const int lqx  = tx & 7;       // 0..7  (4 k's each -> 32 k per iteration)
    const int xkk  = lqx >> 1;     // kk block 0..3
    const int xslt = lqx & 1;      // pair slot
    const int xpo  = (xkk << 8) + (ltok << 3) + xslt;
    const float* xrow = X + (size_t)(t0 + ltok) * Hdim + (lqx << 2);

    // preload c2f and bias (covered by first __syncthreads)
    c2f[tx]       = (float)g_c2d[tx];
    c2f[tx + 256] = (float)g_c2d[tx + 256];
    if (tx < 128) c2f[tx + 512] = (float)g_c2d[tx + 512];
    bs[tx] = bias[tx];

    // ============ Stage 1: h = X @ W + b  (tf32x3, 32-k iterations) =========
    float acc[8][4];
#pragma unroll
    for (int i = 0; i < 8; i++)
#pragma unroll
        for (int j = 0; j < 4; j++) acc[i][j] = 0.f;

    // preload iteration 0 (X 32-k slice + W chunk-pair 0 = 32KB)
    {
        float4 xv = *(const float4*)(xrow);
        Xp[xpo] = xv.x; Xp[xpo + 2] = xv.y; Xp[xpo + 4] = xv.z; Xp[xpo + 6] = xv.w;
#pragma unroll
        for (int q = 0; q < 8; q++)
            cpa16(buf + ((tx + (q << 8)) << 2), g_Wp + ((tx + (q << 8)) << 2));
        CPA_COMMIT();
    }
    CPA_WAIT0();
    __syncthreads();

    for (int kc = 0; kc < 16; kc++) {
        const int cur = kc & 1, nxt = cur ^ 1;
        if (kc < 15) {
            // prefetch X(kc+1) 32-k slice into alternate Xp half
            float4 xv = *(const float4*)(xrow + ((kc + 1) << 5));
            float* xp = Xp + nxt * 1024 + xpo;
            xp[0] = xv.x; xp[2] = xv.y; xp[4] = xv.z; xp[6] = xv.w;
            // prefetch W chunk-pair kc+1 (32KB) into alternate buffer
            const float* sW = g_Wp + ((kc + 1) << 13);
            float* dW = buf + nxt * 8192;
#pragma unroll
            for (int q = 0; q < 8; q++)
                cpa16(dW + ((tx + (q << 8)) << 2), sW + ((tx + (q << 8)) << 2));
            CPA_COMMIT();
        }
        // MMAs on current 32-k slab; split W fragments in registers (exact)
        const float* bw = buf + cur * 8192;
        const float* xp = Xp + cur * 1024;
#pragma unroll
        for (int kk = 0; kk < 4; kk++) {
            float2 pa = *(float2*)&xp[(kk << 8) + (r0 << 3) + lq2];
            float2 pb = *(float2*)&xp[(kk << 8) + (r1 << 3) + lq2];
            unsigned ah[4], al[4];
            split2(pa.x, ah[0], al[0]); split2(pb.x, ah[1], al[1]);
            split2(pa.y, ah[2], al[2]); split2(pb.y, ah[3], al[3]);
#pragma unroll
            for (int s8 = 0; s8 < 8; s8++) {
                float2 pw = *(float2*)&bw[(((kk << 5) + (wn << 3) + s8) << 6) + (lane << 1)];
                unsigned bh[2], bl[2];
                split2(pw.x, bh[0], bl[0]);
                split2(pw.y, bh[1], bl[1]);
                mma_tf32(acc[s8], ah, bh);
                mma_tf32(acc[s8], ah, bl);
                mma_tf32(acc[s8], al, bh);
            }
        }
        CPA_WAIT0();
        __syncthreads();
    }

    // prefetch stage-2 group-0 chunk-0 into buf[0:5120)
    {
#pragma unroll
        for (int q = 0; q < 5; q++)
            cpa16(buf + ((tx + (q << 8)) << 2), g_Cp + ((tx + (q << 8)) << 2));
        CPA_COMMIT();
    }

    // stage-1 epilogue: +bias, h2 partials, store h fragment-paired
    {
        float h2a = 0.f, h2b = 0.f;
#pragma unroll
        for (int s8 = 0; s8 < 8; s8++) {
            int s   = (wn << 3) + s8;
            int col = (s << 3) + lq2;
            float2 bb = *(float2*)&bs[col];
            float v0 = acc[s8][0] + bb.x;
            float v1 = acc[s8][1] + bb.y;
            float v2 = acc[s8][2] + bb.x;
            float v3 = acc[s8][3] + bb.y;
            h2a = fmaf(v0, v0, h2a); h2a = fmaf(v1, v1, h2a);
            h2b = fmaf(v2, v2, h2b); h2b = fmaf(v3, v3, h2b);
            int g = col >> 7, cg = col & 127;
            int kc = cg >> 3, k8 = cg & 7;
            int p0 = k8 & 3, sl0 = k8 >> 2;
            int k8b = k8 + 1, p1 = k8b & 3, sl1 = k8b >> 2;
            int base = (((g << 4) + kc) << 5);
            hsp[((base + r0) << 3) + (p0 << 1) + sl0] = v0;
            hsp[((base + r0) << 3) + (p1 << 1) + sl1] = v1;
            hsp[((base + r1) << 3) + (p0 << 1) + sl0] = v2;
            hsp[((base + r1) << 3) + (p1 << 1) + sl1] = v3;
        }
        h2a += __shfl_xor_sync(0xffffffffu, h2a, 1);
        h2a += __shfl_xor_sync(0xffffffffu, h2a, 2);
        h2b += __shfl_xor_sync(0xffffffffu, h2b, 1);
        h2b += __shfl_xor_sync(0xffffffffu, h2b, 2);
        if ((lane & 3) == 0) {
            h2p[(wn << 5) + r0] = h2a;
            h2p[(wn << 5) + r1] = h2b;
        }
    }
    CPA_WAIT0();
    __syncthreads();

    // ============ Stage 2: hc (tf32x1, pipelined) + exact-rescue argmin =====
    const int bidx  = t0 >> 12;
    const int sbase = t0 & 4095;

    for (int g = 0; g < Gdim; g++) {
        float acc2[10][4];
#pragma unroll
        for (int i = 0; i < 10; i++)
#pragma unroll
            for (int j = 0; j < 4; j++) acc2[i][j] = 0.f;

        for (int kc2 = 0; kc2 < 8; kc2++) {
            const int cur = kc2 & 1, nxt = cur ^ 1;
            if (kc2 < 7) {
                const float* src = g_Cp + ((g << 4) + ((kc2 + 1) << 1)) * 2560;
                float* dst = buf + nxt * 5120;
#pragma unroll
                for (int q = 0; q < 5; q++)
                    cpa16(dst + ((tx + (q << 8)) << 2), src + ((tx + (q << 8)) << 2));
                CPA_COMMIT();
            } else if (g == 0) {
                const float* src = g_Cp + 16 * 2560;   // g=1, chunk 0
                float* dst = buf + nxt * 5120;
#pragma unroll
                for (int q = 0; q < 5; q++)
                    cpa16(dst + ((tx + (q << 8)) << 2), src + ((tx + (q << 8)) << 2));
                CPA_COMMIT();
            }
            const float* bc = buf + cur * 5120;
#pragma unroll
            for (int kk = 0; kk < 2; kk++) {
                int kcx = (kc2 << 1) + kk;
                int hb = (((g << 4) + kcx) << 5);
                float2 pa = *(float2*)&hsp[((hb + r0) << 3) + lq2];
                float2 pb = *(float2*)&hsp[((hb + r1) << 3) + lq2];
                unsigned a[4] = {__float_as_uint(pa.x), __float_as_uint(pb.x),
                                 __float_as_uint(pa.y), __float_as_uint(pb.y)};
#pragma unroll
                for (int j = 0; j < 10; j++) {
                    float2 pw = *(float2*)&bc[((kk * 40 + wn * 10 + j) << 6) + (lane << 1)];
                    unsigned b[2] = {__float_as_uint(pw.x), __float_as_uint(pw.y)};
                    mma_tf32(acc2[j], a, b);
                }
            }
            CPA_WAIT0();
            __syncthreads();
        }

        // ---- epilogue: keys (cached into acc2), distances out, approx min --
        const float h2f0 = h2p[((2 * g) << 5) + r0] + h2p[((2 * g + 1) << 5) + r0];
        const float h2f1 = h2p[((2 * g) << 5) + r1] + h2p[((2 * g + 1) << 5) + r1];
        const size_t row0 = ((size_t)((g * Bdim + bidx) * Sdim) + sbase + r0) * (size_t)Vdim;
        const size_t row1 = ((size_t)((g * Bdim + bidx) * Sdim) + sbase + r1) * (size_t)Vdim;

        float m0 = 1e30f, m1 = 1e30f;
#pragma unroll
        for (int j = 0; j < 10; j++) {
            int v0 = ((wn * 10 + j) << 3) + lq2;
            float2 cc = *(float2*)&c2f[g * Vdim + v0];
            float k00 = fmaf(-2.f, acc2[j][0], cc.x);
            float k01 = fmaf(-2.f, acc2[j][1], cc.y);
            float k10 = fmaf(-2.f, acc2[j][2], cc.x);
            float k11 = fmaf(-2.f, acc2[j][3], cc.y);
            acc2[j][0] = k00; acc2[j][1] = k01;   // cache keys (hc dead now)
            acc2[j][2] = k10; acc2[j][3] = k11;
            *(float2*)(out + DIST_OFF + row0 + v0) = make_float2(h2f0 + k00, h2f0 + k01);
            *(float2*)(out + DIST_OFF + row1 + v0) = make_float2(h2f1 + k10, h2f1 + k11);
            m0 = fminf(m0, fminf(k00, k01));
            m1 = fminf(m1, fminf(k10, k11));
        }
#pragma unroll
        for (int off = 1; off <= 2; off <<= 1) {
            m0 = fminf(m0, __shfl_xor_sync(0xffffffffu, m0, off));
            m1 = fminf(m1, __shfl_xor_sync(0xffffffffu, m1, off));
        }
        if ((lane & 3) == 0) {
            amv[(r0 << 2) + wn] = m0;
            amv[(r1 << 2) + wn] = m1;
        }
        __syncthreads();
        if (tx < 32) {
            float b = amv[tx << 2];
            b = fminf(b, amv[(tx << 2) + 1]);
            b = fminf(b, amv[(tx << 2) + 2]);
            b = fminf(b, amv[(tx << 2) + 3]);
            fmv[tx] = b;
            rcnt[tx] = 0;
        }
        __syncthreads();
        // flag candidates within TAU of the GLOBAL approx min (keys in acc2)
        {
            float thr0 = fmv[r0] + TAU, thr1 = fmv[r1] + TAU;
#pragma unroll
            for (int j = 0; j < 10; j++) {
                int v0 = ((wn * 10 + j) << 3) + lq2;
                if (acc2[j][0] <= thr0) { int s = atomicAdd(&rcnt[r0], 1); if (s < 12) rvid[r0 * 12 + s] = v0; }
                if (acc2[j][1] <= thr0) { int s = atomicAdd(&rcnt[r0], 1); if (s < 12) rvid[r0 * 12 + s] = v0 + 1; }
                if (acc2[j][2] <= thr1) { int s = atomicAdd(&rcnt[r1], 1); if (s < 12) rvid[r1 * 12 + s] = v0; }
                if (acc2[j][3] <= thr1) { int s = atomicAdd(&rcnt[r1], 1); if (s < 12) rvid[r1 * 12 + s] = v0 + 1; }
            }
        }
        __syncthreads();
        // exact rescue: warp w handles rows 4w..4w+3
        {
#pragma unroll
            for (int q = 0; q < 4; q++) {
                int r = (w << 2) + q;
                double hd[4];
#pragma unroll
                for (int e = 0; e < 4; e++) {
                    int d = (lane << 2) + e;
                    int kcq = d >> 3, k8 = d & 7;
                    hd[e] = (double)hsp[(((((g << 4) + kcq) << 5) + r) << 3) + ((k8 & 3) << 1) + (k8 >> 2)];
                }
                int n = rcnt[r]; if (n > 12) n = 12;
                double bk = 1e300; int bv = 0x7fffffff;
                for (int i = 0; i < n; i++) {
                    int v = rvid[r * 12 + i];
                    float4 cv = *(const float4*)(C + ((size_t)(g * Vdim + v)) * Ddim + (lane << 2));
                    double dot = 0.0;
                    dot = fma(hd[0], (double)cv.x, dot);
                    dot = fma(hd[1], (double)cv.y, dot);
                    dot = fma(hd[2], (double)cv.z, dot);
                    dot = fma(hd[3], (double)cv.w, dot);
#pragma unroll
                    for (int off = 16; off >= 1; off >>= 1)
                        dot += __shfl_xor_sync(0xffffffffu, dot, off);
                    double key = fma(-2.0, dot, g_c2d[g * Vdim + v]);
                    if (key < bk || (key == bk && v < bv)) { bk = key; bv = v; }
                }
                if (lane == 0) {
                    fmi[r] = bv;
                    atomicAdd(&g_counts[g * Vdim + bv], 1);
                }
            }
        }
        __syncthreads();
        // encodings + quantized gather
        const int mi0 = fmi[r0], mi1 = fmi[r1];
#pragma unroll
        for (int j = 0; j < 10; j++) {
            int v0 = ((wn * 10 + j) << 3) + lq2;
            *(float2*)(out + ENC_OFF + row0 + v0) =
                make_float2(v0 == mi0 ? 1.f : 0.f, v0 + 1 == mi0 ? 1.f : 0.f);
            *(float2*)(out + ENC_OFF + row1 + v0) =
                make_float2(v0 == mi1 ? 1.f : 0.f, v0 + 1 == mi1 ? 1.f : 0.f);
        }
        {
            int task = tx >> 3, l8 = tx & 7;
            int mi = fmi[task];
            const float4* cs = (const float4*)(C + ((size_t)(g * Vdim + mi)) * Ddim + (l8 << 4));
            float4* qd = (float4*)(out + Q_OFF + (size_t)(t0 + task) * GDdim + g * Ddim + (l8 << 4));
            qd[0] = cs[0]; qd[1] = cs[1]; qd[2] = cs[2]; qd[3] = cs[3];
        }
        __syncthreads();
    }

    // ============ Fused perplexity: last CTA computes it ====================
    __threadfence();
    if (tx == 0) slast[0] = (atomicAdd(&g_done, 1) == NCTA - 1) ? 1 : 0;
    __syncthreads();
    if (slast[0]) {
        __threadfence();
        // reuse c2f region as entropy scratch
        for (int i = tx; i < Gdim * Vdim; i += 256) {
            float p = (float)g_counts[i] * (1.0f / (float)NTOK);
            p = fminf(fmaxf(p, 1e-10f), 1.0f);
            c2f[i] = p * logf(p + 1e-10f);
        }
        __syncthreads();
        if (tx == 0) {
            float s0 = 0.f, s1 = 0.f;
            for (int v = 0; v < Vdim; v++) s0 += c2f[v];
            for (int v = 0; v < Vdim; v++) s1 += c2f[Vdim + v];
            out[PERP_OFF] = 0.5f * (expf(-s0) + expf(-s1));
            g_done = 0;   // reset for next graph replay
        }
    }
}

// ---------------------------------------------------------------------------
extern "C" void kernel_launch(void* const* d_in, const int* in_sizes, int n_in,
                              void* d_out, int out_size) {
    const float* X    = (const float*)d_in[0];
    const float* W    = (const float*)d_in[1];
    const float* bias = (const float*)d_in[2];
    const float* C    = (const float*)d_in[3];
    float* out = (float*)d_out;

    cudaFuncSetAttribute(main_kernel, cudaFuncAttributeMaxDynamicSharedMemorySize,
                         SM_FLOATS * sizeof(float));

    prep_kernel<<<512, 256>>>(W, C);
    main_kernel<<<NCTA, 256, SM_FLOATS * sizeof(float)>>>(X, bias, C, out);
}

// round 15
// speedup vs baseline: 1.6561x; 1.0314x over previous
#include <cuda_runtime.h>

// Problem dims (fixed by the dataset)
#define Bdim 16
#define Sdim 4096
#define Hdim 512
#define Gdim 2
#define Vdim 320
#define Ddim 128
#define GDdim 256
#define NTOK (Bdim * Sdim)           // 65536
#define TOK 32
#define NCTA (NTOK / TOK)            // 2048

// Output layout (concatenated reference returns)
#define Q_OFF    0
#define ENC_OFF  16777216
#define DIST_OFF 58720256
#define PERP_OFF 100663296

#define TAU 0.0625f

// device scratch
__device__ float  g_Wp[Hdim * GDdim];        // W full fp32, fragment-paired (16-k chunks)
__device__ float  g_Cp[Gdim * Vdim * Ddim];  // codevectors rna-tf32, fragment-paired
__device__ double g_c2d[Gdim * Vdim];        // exact ||c||^2
__device__ int    g_counts[Gdim * Vdim];
__device__ int    g_done = 0;

__device__ __forceinline__ void split2(float x, unsigned& hi, unsigned& lo) {
    unsigned xb = __float_as_uint(x);
    hi = xb & 0xFFFFE000u;
    lo = __float_as_uint(x - __uint_as_float(hi));
}

__device__ __forceinline__ void mma_tf32(float* c, const unsigned* a, const unsigned* b) {
    asm volatile(
        "mma.sync.aligned.m16n8k8.row.col.f32.tf32.tf32.f32 "
        "{%0,%1,%2,%3}, {%4,%5,%6,%7}, {%8,%9}, {%0,%1,%2,%3};\n"
        : "+f"(c[0]), "+f"(c[1]), "+f"(c[2]), "+f"(c[3])
        : "r"(a[0]), "r"(a[1]), "r"(a[2]), "r"(a[3]), "r"(b[0]), "r"(b[1]));
}

__device__ __forceinline__ void cpa16(float* s, const float* g) {
    unsigned sa = (unsigned)__cvta_generic_to_shared(s);
    asm volatile("cp.async.cg.shared.global [%0], [%1], 16;\n" :: "r"(sa), "l"(g));
}
#define CPA_COMMIT() asm volatile("cp.async.commit_group;\n" ::: "memory")
#define CPA_WAIT0()  asm volatile("cp.async.wait_group 0;\n" ::: "memory")

// ---------------------------------------------------------------------------
// Prep: counts=0, exact c2, W fragment-paired (full fp32, 16-k chunks), C paired.
// ---------------------------------------------------------------------------
__global__ void prep_kernel(const float* __restrict__ W, const float* __restrict__ C) {
    int tid = blockIdx.x * blockDim.x + threadIdx.x;  // 131072 threads
    if (tid == 0) g_done = 0;
    if (tid < Hdim * GDdim) {
        int e = tid;
        int k = e >> 8, n = e & 255;
        int kc = k >> 4, k16 = k & 15, kk = k16 >> 3, k8 = k16 & 7;
        int s = n >> 3, l = (k8 & 3) + ((n & 7) << 2), slot = k8 >> 2;
        g_Wp[(kc << 12) + (((kk << 5) + s) << 6) + 2 * l + slot] = W[e];
    }
    if (tid < Gdim * Vdim * Ddim) {
        int e = tid;
        int g = e / (Vdim * Ddim);
        int rem = e - g * (Vdim * Ddim);
        int v = rem >> 7, d = rem & 127;
        int kc = d >> 3, k8 = d & 7;
        int s = v >> 3, l = (k8 & 3) + ((v & 7) << 2), slot = k8 >> 2;
        unsigned r;
        asm("cvt.rna.tf32.f32 %0, %1;" : "=r"(r) : "f"(C[e]));
        g_Cp[(((g << 4) + kc) * 40 + s) * 64 + 2 * l + slot] = __uint_as_float(r);
    }
    int gw = tid >> 5, lane = tid & 31;
    if (gw < Gdim * Vdim) {
        float4 cv = *(const float4*)(C + (size_t)gw * Ddim + (lane << 2));
        double s = 0.0;
        s = fma((double)cv.x, (double)cv.x, s);
        s = fma((double)cv.y, (double)cv.y, s);
        s = fma((double)cv.z, (double)cv.z, s);
        s = fma((double)cv.w, (double)cv.w, s);
#pragma unroll
        for (int off = 16; off >= 1; off >>= 1)
            s += __shfl_xor_sync(0xffffffffu, s, off);
        if (lane == 0) { g_c2d[gw] = s; g_counts[gw] = 0; }
    }
}

// ---------------------------------------------------------------------------
// smem layout (float slots) — shrunk for 3 CTAs/SM
// ---------------------------------------------------------------------------
#define SM_HSP   0       // 8192
#define SM_BUF   8192    // 8192: stage1 W 2x4096 (16-k) / stage2 C 2x2560 (1 kcx)
#define SM_XP    16384   // 1024: double-buffered X paired (2x512, 16 k each)
#define SM_BIAS  17408   // 256
#define SM_C2F   17664   // 640 (reused as entropy scratch in fused perp)
#define SM_H2P   18304   // 128
#define SM_AMV   18432   // 128
#define SM_FMV   18560   // 32
#define SM_FMI   18592   // 32 (ints)
#define SM_RCNT  18624   // 32 (ints)
#define SM_RVID  18656   // 384 (ints): 32 rows x 12 slots
#define SM_LAST  19040   // 1 (int)
#define SM_FLOATS 19044  // 76,176 B -> 3 CTAs/SM

extern __shared__ float smem[];

__global__ __launch_bounds__(256, 3)
void main_kernel(const float* __restrict__ X,   // [B*S, 512]
                 const float* __restrict__ bias,// [256]
                 const float* __restrict__ C,   // [2,320,128]
                 float* __restrict__ out)
{
    float*  hsp  = smem + SM_HSP;
    float*  buf  = smem + SM_BUF;
    float*  Xp   = smem + SM_XP;
    float*  bs   = smem + SM_BIAS;
    float*  c2f  = smem + SM_C2F;
    float*  h2p  = smem + SM_H2P;
    float*  amv  = smem + SM_AMV;
    float*  fmv  = smem + SM_FMV;
    int*    fmi  = (int*)(smem + SM_FMI);
    int*    rcnt = (int*)(smem + SM_RCNT);
    int*    rvid = (int*)(smem + SM_RVID);
    int*    slast= (int*)(smem + SM_LAST);

    const int tx   = threadIdx.x;
    const int lane = tx & 31;
    const int w    = tx >> 5;
    const int wm   = w & 1;
    const int wn   = w >> 1;
    const int t0   = blockIdx.x * TOK;
    const int r0   = (wm << 4) + (lane >> 2);
    const int r1   = r0 + 8;
    const int lq2  = (lane & 3) << 1;

    const int ltok = tx >> 3;      // 0..31
    const int lqx  = tx & 7;       // 0..7 (2 k's each, 16 k per iteration)
    const int xk0  = lqx << 1;
    const int xkk  = xk0 >> 3;
    const int xk8a = xk0 & 7, xk8b = (xk0 + 1) & 7;
    const int xpo0 = (xkk << 8) + (ltok << 3) + ((xk8a & 3) << 1) + (xk8a >> 2);
    const int xpo1 = (xkk << 8) + (ltok << 3) + ((xk8b & 3) << 1) + (xk8b >> 2);
    const float* xrow = X + (size_t)(t0 + ltok) * Hdim + xk0;

    // preload c2f and bias (covered by first __syncthreads)
    c2f[tx]       = (float)g_c2d[tx];
    c2f[tx + 256] = (float)g_c2d[tx + 256];
    if (tx < 128) c2f[tx + 512] = (float)g_c2d[tx + 512];
    bs[tx] = bias[tx];

    // ============ Stage 1: h = X @ W + b  (tf32x3, 16-k chunks) =============
    float acc[8][4];
#pragma unroll
    for (int i = 0; i < 8; i++)
#pragma unroll
        for (int j = 0; j < 4; j++) acc[i][j] = 0.f;

    // preload chunk 0 (W 16-k chunk: 4096 floats)
    {
        float2 xv = *(const float2*)(xrow);
        Xp[xpo0] = xv.x; Xp[xpo1] = xv.y;
#pragma unroll
        for (int q = 0; q < 4; q++)
            cpa16(buf + ((tx + (q << 8)) << 2), g_Wp + ((tx + (q << 8)) << 2));
        CPA_COMMIT();
    }
    CPA_WAIT0();
    __syncthreads();

    for (int kc = 0; kc < 32; kc++) {
        const int cur = kc & 1, nxt = cur ^ 1;
        if (kc < 31) {
            float2 xv = *(const float2*)(xrow + ((kc + 1) << 4));
            Xp[nxt * 512 + xpo0] = xv.x;
            Xp[nxt * 512 + xpo1] = xv.y;
            const float* sW = g_Wp + ((kc + 1) << 12);
            float* dW = buf + nxt * 4096;
#pragma unroll
            for (int q = 0; q < 4; q++)
                cpa16(dW + ((tx + (q << 8)) << 2), sW + ((tx + (q << 8)) << 2));
            CPA_COMMIT();
        }
        const float* bw = buf + cur * 4096;
        const float* xp = Xp + cur * 512;
#pragma unroll
        for (int kk = 0; kk < 2; kk++) {
            float2 pa = *(float2*)&xp[(kk << 8) + (r0 << 3) + lq2];
            float2 pb = *(float2*)&xp[(kk << 8) + (r1 << 3) + lq2];
            unsigned ah[4], al[4];
            split2(pa.x, ah[0], al[0]); split2(pb.x, ah[1], al[1]);
            split2(pa.y, ah[2], al[2]); split2(pb.y, ah[3], al[3]);
#pragma unroll
            for (int s8 = 0; s8 < 8; s8++) {
                float2 pw = *(float2*)&bw[(((kk << 5) + (wn << 3) + s8) << 6) + (lane << 1)];
                unsigned bh[2], bl[2];
                split2(pw.x, bh[0], bl[0]);
                split2(pw.y, bh[1], bl[1]);
                mma_tf32(acc[s8], ah, bh);
                mma_tf32(acc[s8], ah, bl);
                mma_tf32(acc[s8], al, bh);
            }
        }
        CPA_WAIT0();
        __syncthreads();
    }

    // prefetch stage-2 group-0 kcx-0 into buf[0:2560)
    {
#pragma unroll
        for (int q = 0; q < 3; q++) {
            int idx = tx + (q << 8);
            if (idx < 640)
                cpa16(buf + (idx << 2), g_Cp + (idx << 2));
        }
        CPA_COMMIT();
    }

    // stage-1 epilogue: +bias, h2 partials, store h fragment-paired
    {
        float h2a = 0.f, h2b = 0.f;
#pragma unroll
        for (int s8 = 0; s8 < 8; s8++) {
            int s   = (wn << 3) + s8;
            int col = (s << 3) + lq2;
            float2 bb = *(float2*)&bs[col];
            float v0 = acc[s8][0] + bb.x;
            float v1 = acc[s8][1] + bb.y;
            float v2 = acc[s8][2] + bb.x;
            float v3 = acc[s8][3] + bb.y;
            h2a = fmaf(v0, v0, h2a); h2a = fmaf(v1, v1, h2a);
            h2b = fmaf(v2, v2, h2b); h2b = fmaf(v3, v3, h2b);
            int g = col >> 7, cg = col & 127;
            int kc = cg >> 3, k8 = cg & 7;
            int p0 = k8 & 3, sl0 = k8 >> 2;
            int k8b = k8 + 1, p1 = k8b & 3, sl1 = k8b >> 2;
            int base = (((g << 4) + kc) << 5);
            hsp[((base + r0) << 3) + (p0 << 1) + sl0] = v0;
            hsp[((base + r0) << 3) + (p1 << 1) + sl1] = v1;
            hsp[((base + r1) << 3) + (p0 << 1) + sl0] = v2;
            hsp[((base + r1) << 3) + (p1 << 1) + sl1] = v3;
        }
        h2a += __shfl_xor_sync(0xffffffffu, h2a, 1);
        h2a += __shfl_xor_sync(0xffffffffu, h2a, 2);
        h2b += __shfl_xor_sync(0xffffffffu, h2b, 1);
        h2b += __shfl_xor_sync(0xffffffffu, h2b, 2);
        if ((lane & 3) == 0) {
            h2p[(wn << 5) + r0] = h2a;
            h2p[(wn << 5) + r1] = h2b;
        }
    }
    CPA_WAIT0();
    __syncthreads();

    // ============ Stage 2: hc (tf32x1, single-kcx chunks) + rescue ==========
    const int bidx  = t0 >> 12;
    const int sbase = t0 & 4095;

    for (int g = 0; g < Gdim; g++) {
        float acc2[10][4];
#pragma unroll
        for (int i = 0; i < 10; i++)
#pragma unroll
            for (int j = 0; j < 4; j++) acc2[i][j] = 0.f;

        for (int kcx = 0; kcx < 16; kcx++) {
            const int cur = kcx & 1, nxt = cur ^ 1;
            const bool havenext = (kcx < 15) || (g == 0);
            if (havenext) {
                const float* src = (kcx < 15)
                    ? g_Cp + ((g << 4) + kcx + 1) * 2560
                    : g_Cp + 16 * 2560;              // g=1, kcx 0
                float* dst = buf + nxt * 2560;
#pragma unroll
                for (int q = 0; q < 3; q++) {
                    int idx = tx + (q << 8);
                    if (idx < 640)
                        cpa16(dst + (idx << 2), src + (idx << 2));
                }
                CPA_COMMIT();
            }
            const float* bc = buf + cur * 2560;
            int hb = (((g << 4) + kcx) << 5);
            float2 pa = *(float2*)&hsp[((hb + r0) << 3) + lq2];
            float2 pb = *(float2*)&hsp[((hb + r1) << 3) + lq2];
            unsigned a[4] = {__float_as_uint(pa.x), __float_as_uint(pb.x),
                             __float_as_uint(pa.y), __float_as_uint(pb.y)};
#pragma unroll
            for (int j = 0; j < 10; j++) {
                float2 pw = *(float2*)&bc[((wn * 10 + j) << 6) + (lane << 1)];
                unsigned b[2] = {__float_as_uint(pw.x), __float_as_uint(pw.y)};
                mma_tf32(acc2[j], a, b);
            }
            CPA_WAIT0();
            __syncthreads();
        }

        // ---- epilogue: keys (cached into acc2), distances out, approx min --
        const float h2f0 = h2p[((2 * g) << 5) + r0] + h2p[((2 * g + 1) << 5) + r0];
        const float h2f1 = h2p[((2 * g) << 5) + r1] + h2p[((2 * g + 1) << 5) + r1];
        const size_t row0 = ((size_t)((g * Bdim + bidx) * Sdim) + sbase + r0) * (size_t)Vdim;
        const size_t row1 = ((size_t)((g * Bdim + bidx) * Sdim) + sbase + r1) * (size_t)Vdim;

        float m0 = 1e30f, m1 = 1e30f;
#pragma unroll
        for (int j = 0; j < 10; j++) {
            int v0 = ((wn * 10 + j) << 3) + lq2;
            float2 cc = *(float2*)&c2f[g * Vdim + v0];
            float k00 = fmaf(-2.f, acc2[j][0], cc.x);
            float k01 = fmaf(-2.f, acc2[j][1], cc.y);
            float k10 = fmaf(-2.f, acc2[j][2], cc.x);
            float k11 = fmaf(-2.f, acc2[j][3], cc.y);
            acc2[j][0] = k00; acc2[j][1] = k01;
            acc2[j][2] = k10; acc2[j][3] = k11;
            *(float2*)(out + DIST_OFF + row0 + v0) = make_float2(h2f0 + k00, h2f0 + k01);
            *(float2*)(out + DIST_OFF + row1 + v0) = make_float2(h2f1 + k10, h2f1 + k11);
            m0 = fminf(m0, fminf(k00, k01));
            m1 = fminf(m1, fminf(k10, k11));
        }
#pragma unroll
        for (int off = 1; off <= 2; off <<= 1) {
            m0 = fminf(m0, __shfl_xor_sync(0xffffffffu, m0, off));
            m1 = fminf(m1, __shfl_xor_sync(0xffffffffu, m1, off));
        }
        if ((lane & 3) == 0) {
            amv[(r0 << 2) + wn] = m0;
            amv[(r1 << 2) + wn] = m1;
        }
        __syncthreads();
        if (tx < 32) {
            float b = amv[tx << 2];
            b = fminf(b, amv[(tx << 2) + 1]);
            b = fminf(b, amv[(tx << 2) + 2]);
            b = fminf(b, amv[(tx << 2) + 3]);
            fmv[tx] = b;
            rcnt[tx] = 0;
        }
        __syncthreads();
        // flag candidates within TAU of the GLOBAL approx min
        {
            float thr0 = fmv[r0] + TAU, thr1 = fmv[r1] + TAU;
#pragma unroll
            for (int j = 0; j < 10; j++) {
                int v0 = ((wn * 10 + j) << 3) + lq2;
                if (acc2[j][0] <= thr0) { int s = atomicAdd(&rcnt[r0], 1); if (s < 12) rvid[r0 * 12 + s] = v0; }
                if (acc2[j][1] <= thr0) { int s = atomicAdd(&rcnt[r0], 1); if (s < 12) rvid[r0 * 12 + s] = v0 + 1; }
                if (acc2[j][2] <= thr1) { int s = atomicAdd(&rcnt[r1], 1); if (s < 12) rvid[r1 * 12 + s] = v0; }
                if (acc2[j][3] <= thr1) { int s = atomicAdd(&rcnt[r1], 1); if (s < 12) rvid[r1 * 12 + s] = v0 + 1; }
            }
        }
        __syncthreads();
        // exact rescue: warp w handles rows 4w..4w+3
        {
#pragma unroll
            for (int q = 0; q < 4; q++) {
                int r = (w << 2) + q;
                double hd[4];
#pragma unroll
                for (int e = 0; e < 4; e++) {
                    int d = (lane << 2) + e;
                    int kcq = d >> 3, k8 = d & 7;
                    hd[e] = (double)hsp[(((((g << 4) + kcq) << 5) + r) << 3) + ((k8 & 3) << 1) + (k8 >> 2)];
                }
                int n = rcnt[r]; if (n > 12) n = 12;
                double bk = 1e300; int bv = 0x7fffffff;
                for (int i = 0; i < n; i++) {
                    int v = rvid[r * 12 + i];
                    float4 cv = *(const float4*)(C + ((size_t)(g * Vdim + v)) * Ddim + (lane << 2));
                    double dot = 0.0;
                    dot = fma(hd[0], (double)cv.x, dot);
                    dot = fma(hd[1], (double)cv.y, dot);
                    dot = fma(hd[2], (double)cv.z, dot);
                    dot = fma(hd[3], (double)cv.w, dot);
#pragma unroll
                    for (int off = 16; off >= 1; off >>= 1)
                        dot += __shfl_xor_sync(0xffffffffu, dot, off);
                    double key = fma(-2.0, dot, g_c2d[g * Vdim + v]);
                    if (key < bk || (key == bk && v < bv)) { bk = key; bv = v; }
                }
                if (lane == 0) {
                    fmi[r] = bv;
                    atomicAdd(&g_counts[g * Vdim + bv], 1);
                }
            }
        }
        __syncthreads();
        // encodings + quantized gather
        const int mi0 = fmi[r0], mi1 = fmi[r1];
#pragma unroll
        for (int j = 0; j < 10; j++) {
            int v0 = ((wn * 10 + j) << 3) + lq2;
            *(float2*)(out + ENC_OFF + row0 + v0) =
                make_float2(v0 == mi0 ? 1.f : 0.f, v0 + 1 == mi0 ? 1.f : 0.f);
            *(float2*)(out + ENC_OFF + row1 + v0) =
                make_float2(v0 == mi1 ? 1.f : 0.f, v0 + 1 == mi1 ? 1.f : 0.f);
        }
        {
            int task = tx >> 3, l8 = tx & 7;
            int mi = fmi[task];
            const float4* cs = (const float4*)(C + ((size_t)(g * Vdim + mi)) * Ddim + (l8 << 4));
            float4* qd = (float4*)(out + Q_OFF + (size_t)(t0 + task) * GDdim + g * Ddim + (l8 << 4));
            qd[0] = cs[0]; qd[1] = cs[1]; qd[2] = cs[2]; qd[3] = cs[3];
        }
        __syncthreads();
    }

    // ============ Fused perplexity: last CTA computes it ====================
    __threadfence();
    if (tx == 0) slast[0] = (atomicAdd(&g_done, 1) == NCTA - 1) ? 1 : 0;
    __syncthreads();
    if (slast[0]) {
        __threadfence();
        for (int i = tx; i < Gdim * Vdim; i += 256) {
            float p = (float)g_counts[i] * (1.0f / (float)NTOK);
            p = fminf(fmaxf(p, 1e-10f), 1.0f);
            c2f[i] = p * logf(p + 1e-10f);
        }
        __syncthreads();
        if (tx == 0) {
            float s0 = 0.f, s1 = 0.f;
            for (int v = 0; v < Vdim; v++) s0 += c2f[v];
            for (int v = 0; v < Vdim; v++) s1 += c2f[Vdim + v];
            out[PERP_OFF] = 0.5f * (expf(-s0) + expf(-s1));
            g_done = 0;   // reset for next graph replay
        }
    }
}

// ---------------------------------------------------------------------------
extern "C" void kernel_launch(void* const* d_in, const int* in_sizes, int n_in,
                              void* d_out, int out_size) {
    const float* X    = (const float*)d_in[0];
    const float* W    = (const float*)d_in[1];
    const float* bias = (const float*)d_in[2];
    const float* C    = (const float*)d_in[3];
    float* out = (float*)d_out;

    cudaFuncSetAttribute(main_kernel, cudaFuncAttributeMaxDynamicSharedMemorySize,
                         SM_FLOATS * sizeof(float));

    prep_kernel<<<512, 256>>>(W, C);
    main_kernel<<<NCTA, 256, SM_FLOATS * sizeof(float)>>>(X, bias, C, out);
}

// round 16
// speedup vs baseline: 1.7043x; 1.0291x over previous
#include <cuda_runtime.h>

// Problem dims (fixed by the dataset)
#define Bdim 16
#define Sdim 4096
#define Hdim 512
#define Gdim 2
#define Vdim 320
#define Ddim 128
#define GDdim 256
#define NTOK (Bdim * Sdim)           // 65536
#define TOK 32
#define NCTA (NTOK / TOK)            // 2048

// Output layout (concatenated reference returns)
#define Q_OFF    0
#define ENC_OFF  16777216
#define DIST_OFF 58720256
#define PERP_OFF 100663296

#define TAU 0.0625f

// device scratch
__device__ float  g_Wp[Hdim * GDdim];        // W full fp32, fragment-paired (16-k chunks)
__device__ float  g_Cp[Gdim * Vdim * Ddim];  // codevectors rna-tf32, fragment-paired
__device__ double g_c2d[Gdim * Vdim];        // exact ||c||^2
__device__ int    g_counts[Gdim * Vdim];
__device__ int    g_done = 0;

__device__ __forceinline__ void split2(float x, unsigned& hi, unsigned& lo) {
    unsigned xb = __float_as_uint(x);
    hi = xb & 0xFFFFE000u;
    lo = __float_as_uint(x - __uint_as_float(hi));
}

__device__ __forceinline__ void mma_tf32(float* c, const unsigned* a, const unsigned* b) {
    asm volatile(
        "mma.sync.aligned.m16n8k8.row.col.f32.tf32.tf32.f32 "
        "{%0,%1,%2,%3}, {%4,%5,%6,%7}, {%8,%9}, {%0,%1,%2,%3};\n"
        : "+f"(c[0]), "+f"(c[1]), "+f"(c[2]), "+f"(c[3])
        : "r"(a[0]), "r"(a[1]), "r"(a[2]), "r"(a[3]), "r"(b[0]), "r"(b[1]));
}

__device__ __forceinline__ void cpa16(float* s, const float* g) {
    unsigned sa = (unsigned)__cvta_generic_to_shared(s);
    asm volatile("cp.async.cg.shared.global [%0], [%1], 16;\n" :: "r"(sa), "l"(g));
}
#define CPA_COMMIT() asm volatile("cp.async.commit_group;\n" ::: "memory")
#define CPA_WAIT0()  asm volatile("cp.async.wait_group 0;\n" ::: "memory")

// ---------------------------------------------------------------------------
// Prep: counts=0, exact c2, W fragment-paired (full fp32, 16-k chunks), C paired.
// ---------------------------------------------------------------------------
__global__ void prep_kernel(const float* __restrict__ W, const float* __restrict__ C) {
    int tid = blockIdx.x * blockDim.x + threadIdx.x;  // 131072 threads
    if (tid == 0) g_done = 0;
    if (tid < Hdim * GDdim) {
        int e = tid;
        int k = e >> 8, n = e & 255;
        int kc = k >> 4, k16 = k & 15, kk = k16 >> 3, k8 = k16 & 7;
        int s = n >> 3, l = (k8 & 3) + ((n & 7) << 2), slot = k8 >> 2;
        g_Wp[(kc << 12) + (((kk << 5) + s) << 6) + 2 * l + slot] = W[e];
    }
    if (tid < Gdim * Vdim * Ddim) {
        int e = tid;
        int g = e / (Vdim * Ddim);
        int rem = e - g * (Vdim * Ddim);
        int v = rem >> 7, d = rem & 127;
        int kc = d >> 3, k8 = d & 7;
        int s = v >> 3, l = (k8 & 3) + ((v & 7) << 2), slot = k8 >> 2;
        unsigned r;
        asm("cvt.rna.tf32.f32 %0, %1;" : "=r"(r) : "f"(C[e]));
        g_Cp[(((g << 4) + kc) * 40 + s) * 64 + 2 * l + slot] = __uint_as_float(r);
    }
    int gw = tid >> 5, lane = tid & 31;
    if (gw < Gdim * Vdim) {
        float4 cv = *(const float4*)(C + (size_t)gw * Ddim + (lane << 2));
        double s = 0.0;
        s = fma((double)cv.x, (double)cv.x, s);
        s = fma((double)cv.y, (double)cv.y, s);
        s = fma((double)cv.z, (double)cv.z, s);
        s = fma((double)cv.w, (double)cv.w, s);
#pragma unroll
        for (int off = 16; off >= 1; off >>= 1)
            s += __shfl_xor_sync(0xffffffffu, s, off);
        if (lane == 0) { g_c2d[gw] = s; g_counts[gw] = 0; }
    }
}

// ---------------------------------------------------------------------------
// smem layout (float slots) — 3 CTAs/SM; stage-2 reads C direct from L2
// ---------------------------------------------------------------------------
#define SM_HSP   0       // 8192
#define SM_BUF   8192    // 8192: stage1 W 2x4096 (16-k chunks)
#define SM_XP    16384   // 1024: double-buffered X paired (2x512, 16 k each)
#define SM_BIAS  17408   // 256
#define SM_C2F   17664   // 640 (reused as entropy scratch in fused perp)
#define SM_H2P   18304   // 128
#define SM_AMV   18432   // 128
#define SM_FMV   18560   // 32
#define SM_FMI   18592   // 32 (ints)
#define SM_RCNT  18624   // 32 (ints)
#define SM_RVID  18656   // 384 (ints): 32 rows x 12 slots
#define SM_LAST  19040   // 1 (int)
#define SM_FLOATS 19044  // 76,176 B -> 3 CTAs/SM

extern __shared__ float smem[];

__global__ __launch_bounds__(256, 3)
void main_kernel(const float* __restrict__ X,   // [B*S, 512]
                 const float* __restrict__ bias,// [256]
                 const float* __restrict__ C,   // [2,320,128]
                 float* __restrict__ out)
{
    float*  hsp  = smem + SM_HSP;
    float*  buf  = smem + SM_BUF;
    float*  Xp   = smem + SM_XP;
    float*  bs   = smem + SM_BIAS;
    float*  c2f  = smem + SM_C2F;
    float*  h2p  = smem + SM_H2P;
    float*  amv  = smem + SM_AMV;
    float*  fmv  = smem + SM_FMV;
    int*    fmi  = (int*)(smem + SM_FMI);
    int*    rcnt = (int*)(smem + SM_RCNT);
    int*    rvid = (int*)(smem + SM_RVID);
    int*    slast= (int*)(smem + SM_LAST);

    const int tx   = threadIdx.x;
    const int lane = tx & 31;
    const int w    = tx >> 5;
    const int wm   = w & 1;
    const int wn   = w >> 1;
    const int t0   = blockIdx.x * TOK;
    const int r0   = (wm << 4) + (lane >> 2);
    const int r1   = r0 + 8;
    const int lq2  = (lane & 3) << 1;

    const int ltok = tx >> 3;      // 0..31
    const int lqx  = tx & 7;       // 0..7 (2 k's each, 16 k per iteration)
    const int xk0  = lqx << 1;
    const int xkk  = xk0 >> 3;
    const int xk8a = xk0 & 7, xk8b = (xk0 + 1) & 7;
    const int xpo0 = (xkk << 8) + (ltok << 3) + ((xk8a & 3) << 1) + (xk8a >> 2);
    const int xpo1 = (xkk << 8) + (ltok << 3) + ((xk8b & 3) << 1) + (xk8b >> 2);
    const float* xrow = X + (size_t)(t0 + ltok) * Hdim + xk0;

    // preload c2f and bias (covered by first __syncthreads)
    c2f[tx]       = (float)g_c2d[tx];
    c2f[tx + 256] = (float)g_c2d[tx + 256];
    if (tx < 128) c2f[tx + 512] = (float)g_c2d[tx + 512];
    bs[tx] = bias[tx];

    // ============ Stage 1: h = X @ W + b  (tf32x3, 16-k chunks) =============
    float acc[8][4];
#pragma unroll
    for (int i = 0; i < 8; i++)
#pragma unroll
        for (int j = 0; j < 4; j++) acc[i][j] = 0.f;

    // preload chunk 0 (W 16-k chunk: 4096 floats)
    {
        float2 xv = *(const float2*)(xrow);
        Xp[xpo0] = xv.x; Xp[xpo1] = xv.y;
#pragma unroll
        for (int q = 0; q < 4; q++)
            cpa16(buf + ((tx + (q << 8)) << 2), g_Wp + ((tx + (q << 8)) << 2));
        CPA_COMMIT();
    }
    CPA_WAIT0();
    __syncthreads();

    for (int kc = 0; kc < 32; kc++) {
        const int cur = kc & 1, nxt = cur ^ 1;
        if (kc < 31) {
            float2 xv = *(const float2*)(xrow + ((kc + 1) << 4));
            Xp[nxt * 512 + xpo0] = xv.x;
            Xp[nxt * 512 + xpo1] = xv.y;
            const float* sW = g_Wp + ((kc + 1) << 12);
            float* dW = buf + nxt * 4096;
#pragma unroll
            for (int q = 0; q < 4; q++)
                cpa16(dW + ((tx + (q << 8)) << 2), sW + ((tx + (q << 8)) << 2));
            CPA_COMMIT();
        }
        const float* bw = buf + cur * 4096;
        const float* xp = Xp + cur * 512;
#pragma unroll
        for (int kk = 0; kk < 2; kk++) {
            float2 pa = *(float2*)&xp[(kk << 8) + (r0 << 3) + lq2];
            float2 pb = *(float2*)&xp[(kk << 8) + (r1 << 3) + lq2];
            unsigned ah[4], al[4];
            split2(pa.x, ah[0], al[0]); split2(pb.x, ah[1], al[1]);
            split2(pa.y, ah[2], al[2]); split2(pb.y, ah[3], al[3]);
#pragma unroll
            for (int s8 = 0; s8 < 8; s8++) {
                float2 pw = *(float2*)&bw[(((kk << 5) + (wn << 3) + s8) << 6) + (lane << 1)];
                unsigned bh[2], bl[2];
                split2(pw.x, bh[0], bl[0]);
                split2(pw.y, bh[1], bl[1]);
                mma_tf32(acc[s8], ah, bh);
                mma_tf32(acc[s8], ah, bl);
                mma_tf32(acc[s8], al, bh);
            }
        }
        CPA_WAIT0();
        __syncthreads();
    }

    // stage-1 epilogue: +bias, h2 partials, store h fragment-paired
    {
        float h2a = 0.f, h2b = 0.f;
#pragma unroll
        for (int s8 = 0; s8 < 8; s8++) {
            int s   = (wn << 3) + s8;
            int col = (s << 3) + lq2;
            float2 bb = *(float2*)&bs[col];
            float v0 = acc[s8][0] + bb.x;
            float v1 = acc[s8][1] + bb.y;
            float v2 = acc[s8][2] + bb.x;
            float v3 = acc[s8][3] + bb.y;
            h2a = fmaf(v0, v0, h2a); h2a = fmaf(v1, v1, h2a);
            h2b = fmaf(v2, v2, h2b); h2b = fmaf(v3, v3, h2b);
            int g = col >> 7, cg = col & 127;
            int kc = cg >> 3, k8 = cg & 7;
            int p0 = k8 & 3, sl0 = k8 >> 2;
            int k8b = k8 + 1, p1 = k8b & 3, sl1 = k8b >> 2;
            int base = (((g << 4) + kc) << 5);
            hsp[((base + r0) << 3) + (p0 << 1) + sl0] = v0;
            hsp[((base + r0) << 3) + (p1 << 1) + sl1] = v1;
            hsp[((base + r1) << 3) + (p0 << 1) + sl0] = v2;
            hsp[((base + r1) << 3) + (p1 << 1) + sl1] = v3;
        }
        h2a += __shfl_xor_sync(0xffffffffu, h2a, 1);
        h2a += __shfl_xor_sync(0xffffffffu, h2a, 2);
        h2b += __shfl_xor_sync(0xffffffffu, h2b, 1);
        h2b += __shfl_xor_sync(0xffffffffu, h2b, 2);
        if ((lane & 3) == 0) {
            h2p[(wn << 5) + r0] = h2a;
            h2p[(wn << 5) + r1] = h2b;
        }
    }
    __syncthreads();

    // ============ Stage 2: hc (tf32x1, C direct from L2, no barriers) =======
    const int bidx  = t0 >> 12;
    const int sbase = t0 & 4095;

    for (int g = 0; g < Gdim; g++) {
        float acc2[10][4];
#pragma unroll
        for (int i = 0; i < 10; i++)
#pragma unroll
            for (int j = 0; j < 4; j++) acc2[i][j] = 0.f;

        {
            // this warp's C fragment base: slice s = wn*10..wn*10+9
            const float* cb = g_Cp + (((g << 4) * 40 + wn * 10) << 6) + (lane << 1);
            for (int kcx = 0; kcx < 16; kcx++) {
                int hb = (((g << 4) + kcx) << 5);
                float2 pa = *(float2*)&hsp[((hb + r0) << 3) + lq2];
                float2 pb = *(float2*)&hsp[((hb + r1) << 3) + lq2];
                unsigned a[4] = {__float_as_uint(pa.x), __float_as_uint(pb.x),
                                 __float_as_uint(pa.y), __float_as_uint(pb.y)};
                const float* cx = cb + ((kcx * 40) << 6);
#pragma unroll
                for (int j = 0; j < 10; j++) {
                    float2 pw = *(const float2*)(cx + (j << 6));
                    unsigned b[2] = {__float_as_uint(pw.x), __float_as_uint(pw.y)};
                    mma_tf32(acc2[j], a, b);
                }
            }
        }

        // ---- epilogue: keys (cached into acc2), distances out, approx min --
        const float h2f0 = h2p[((2 * g) << 5) + r0] + h2p[((2 * g + 1) << 5) + r0];
        const float h2f1 = h2p[((2 * g) << 5) + r1] + h2p[((2 * g + 1) << 5) + r1];
        const size_t row0 = ((size_t)((g * Bdim + bidx) * Sdim) + sbase + r0) * (size_t)Vdim;
        const size_t row1 = ((size_t)((g * Bdim + bidx) * Sdim) + sbase + r1) * (size_t)Vdim;

        float m0 = 1e30f, m1 = 1e30f;
#pragma unroll
        for (int j = 0; j < 10; j++) {
            int v0 = ((wn * 10 + j) << 3) + lq2;
            float2 cc = *(float2*)&c2f[g * Vdim + v0];
            float k00 = fmaf(-2.f, acc2[j][0], cc.x);
            float k01 = fmaf(-2.f, acc2[j][1], cc.y);
            float k10 = fmaf(-2.f, acc2[j][2], cc.x);
            float k11 = fmaf(-2.f, acc2[j][3], cc.y);
            acc2[j][0] = k00; acc2[j][1] = k01;
            acc2[j][2] = k10; acc2[j][3] = k11;
            *(float2*)(out + DIST_OFF + row0 + v0) = make_float2(h2f0 + k00, h2f0 + k01);
            *(float2*)(out + DIST_OFF + row1 + v0) = make_float2(h2f1 + k10, h2f1 + k11);
            m0 = fminf(m0, fminf(k00, k01));
            m1 = fminf(m1, fminf(k10, k11));
        }
#pragma unroll
        for (int off = 1; off <= 2; off <<= 1) {
            m0 = fminf(m0, __shfl_xor_sync(0xffffffffu, m0, off));
            m1 = fminf(m1, __shfl_xor_sync(0xffffffffu, m1, off));
        }
        if ((lane & 3) == 0) {
            amv[(r0 << 2) + wn] = m0;
            amv[(r1 << 2) + wn] = m1;
        }
        __syncthreads();
        if (tx < 32) {
            float b = amv[tx << 2];
            b = fminf(b, amv[(tx << 2) + 1]);
            b = fminf(b, amv[(tx << 2) + 2]);
            b = fminf(b, amv[(tx << 2) + 3]);
            fmv[tx] = b;
            rcnt[tx] = 0;
        }
        __syncthreads();
        // flag candidates within TAU of the GLOBAL approx min
        {
            float thr0 = fmv[r0] + TAU, thr1 = fmv[r1] + TAU;
#pragma unroll
            for (int j = 0; j < 10; j++) {
                int v0 = ((wn * 10 + j) << 3) + lq2;
                if (acc2[j][0] <= thr0) { int s = atomicAdd(&rcnt[r0], 1); if (s < 12) rvid[r0 * 12 + s] = v0; }
                if (acc2[j][1] <= thr0) { int s = atomicAdd(&rcnt[r0], 1); if (s < 12) rvid[r0 * 12 + s] = v0 + 1; }
                if (acc2[j][2] <= thr1) { int s = atomicAdd(&rcnt[r1], 1); if (s < 12) rvid[r1 * 12 + s] = v0; }
                if (acc2[j][3] <= thr1) { int s = atomicAdd(&rcnt[r1], 1); if (s < 12) rvid[r1 * 12 + s] = v0 + 1; }
            }
        }
        __syncthreads();
        // exact rescue: warp w handles rows 4w..4w+3
        {
#pragma unroll
            for (int q = 0; q < 4; q++) {
                int r = (w << 2) + q;
                double hd[4];
#pragma unroll
                for (int e = 0; e < 4; e++) {
                    int d = (lane << 2) + e;
                    int kcq = d >> 3, k8 = d & 7;
                    hd[e] = (double)hsp[(((((g << 4) + kcq) << 5) + r) << 3) + ((k8 & 3) << 1) + (k8 >> 2)];
                }
                int n = rcnt[r]; if (n > 12) n = 12;
                double bk = 1e300; int bv = 0x7fffffff;
                for (int i = 0; i < n; i++) {
                    int v = rvid[r * 12 + i];
                    float4 cv = *(const float4*)(C + ((size_t)(g * Vdim + v)) * Ddim + (lane << 2));
                    double dot = 0.0;
                    dot = fma(hd[0], (double)cv.x, dot);
                    dot = fma(hd[1], (double)cv.y, dot);
                    dot = fma(hd[2], (double)cv.z, dot);
                    dot = fma(hd[3], (double)cv.w, dot);
#pragma unroll
                    for (int off = 16; off >= 1; off >>= 1)
                        dot += __shfl_xor_sync(0xffffffffu, dot, off);
                    double key = fma(-2.0, dot, g_c2d[g * Vdim + v]);
                    if (key < bk || (key == bk && v < bv)) { bk = key; bv = v; }
                }
                if (lane == 0) {
                    fmi[r] = bv;
                    atomicAdd(&g_counts[g * Vdim + bv], 1);
                }
            }
        }
        __syncthreads();
        // encodings + quantized gather
        const int mi0 = fmi[r0], mi1 = fmi[r1];
#pragma unroll
        for (int j = 0; j < 10; j++) {
            int v0 = ((wn * 10 + j) << 3) + lq2;
            *(float2*)(out + ENC_OFF + row0 + v0) =
                make_float2(v0 == mi0 ? 1.f : 0.f, v0 + 1 == mi0 ? 1.f : 0.f);
            *(float2*)(out + ENC_OFF + row1 + v0) =
                make_float2(v0 == mi1 ? 1.f : 0.f, v0 + 1 == mi1 ? 1.f : 0.f);
        }
        {
            int task = tx >> 3, l8 = tx & 7;
            int mi = fmi[task];
            const float4* cs = (const float4*)(C + ((size_t)(g * Vdim + mi)) * Ddim + (l8 << 4));
            float4* qd = (float4*)(out + Q_OFF + (size_t)(t0 + task) * GDdim + g * Ddim + (l8 << 4));
            qd[0] = cs[0]; qd[1] = cs[1]; qd[2] = cs[2]; qd[3] = cs[3];
        }
        __syncthreads();
    }

    // ============ Fused perplexity: last CTA computes it ====================
    __threadfence();
    if (tx == 0) slast[0] = (atomicAdd(&g_done, 1) == NCTA - 1) ? 1 : 0;
    __syncthreads();
    if (slast[0]) {
        __threadfence();
        for (int i = tx; i < Gdim * Vdim; i += 256) {
            float p = (float)g_counts[i] * (1.0f / (float)NTOK);
            p = fminf(fmaxf(p, 1e-10f), 1.0f);
            c2f[i] = p * logf(p + 1e-10f);
        }
        __syncthreads();
        if (tx == 0) {
            float s0 = 0.f, s1 = 0.f;
            for (int v = 0; v < Vdim; v++) s0 += c2f[v];
            for (int v = 0; v < Vdim; v++) s1 += c2f[Vdim + v];
            out[PERP_OFF] = 0.5f * (expf(-s0) + expf(-s1));
            g_done = 0;   // reset for next graph replay
        }
    }
}

// ---------------------------------------------------------------------------
extern "C" void kernel_launch(void* const* d_in, const int* in_sizes, int n_in,
                              void* d_out, int out_size) {
    const float* X    = (const float*)d_in[0];
    const float* W    = (const float*)d_in[1];
    const float* bias = (const float*)d_in[2];
    const float* C    = (const float*)d_in[3];
    float* out = (float*)d_out;

    cudaFuncSetAttribute(main_kernel, cudaFuncAttributeMaxDynamicSharedMemorySize,
                         SM_FLOATS * sizeof(float));

    prep_kernel<<<512, 256>>>(W, C);
    main_kernel<<<NCTA, 256, SM_FLOATS * sizeof(float)>>>(X, bias, C, out);
}